// round 6
// baseline (speedup 1.0000x reference)
#include <cuda_runtime.h>
#include <cuda_fp16.h>
#include <math.h>

#define B_SIZE    8192
#define K_FEATS   32
#define FT_OUT    512
#define BUCKETS   8
#define FT_VOCAB  40960
#define FFT_VOCAB 640

// Combined table in fp16: comb[i][f] = (half)(ft_w[i][f] + fft_w[i % 640][f])
// 40960 * 512 halves = 41.9 MB (static __device__ scratch).
__device__ __half g_comb[FT_VOCAB * FT_OUT];

// ---------------------------------------------------------------------------
// Pass 1: build combined fp16 table (DRAM-bound, near floor).
// ---------------------------------------------------------------------------
__global__ void combine_kernel(const float4* __restrict__ ftw,
                               const float4* __restrict__ fftw) {
    int i = blockIdx.x * blockDim.x + threadIdx.x;          // group of 8 floats
    const int ngroups = FT_VOCAB * (FT_OUT / 8);
    if (i >= ngroups) return;
    int row  = i >> 6;                                      // 64 groups per row
    int g    = i & 63;
    int frow = row % FFT_VOCAB;

    float4 a0 = __ldcs(ftw + (size_t)i * 2);
    float4 a1 = __ldcs(ftw + (size_t)i * 2 + 1);
    const float4* fr = fftw + (size_t)frow * (FT_OUT / 4) + g * 2;
    float4 b0 = __ldg(fr);
    float4 b1 = __ldg(fr + 1);

    __half2 h0 = __floats2half2_rn(a0.x + b0.x, a0.y + b0.y);
    __half2 h1 = __floats2half2_rn(a0.z + b0.z, a0.w + b0.w);
    __half2 h2 = __floats2half2_rn(a1.x + b1.x, a1.y + b1.y);
    __half2 h3 = __floats2half2_rn(a1.z + b1.z, a1.w + b1.w);

    uint4 pack;
    pack.x = *reinterpret_cast<unsigned int*>(&h0);
    pack.y = *reinterpret_cast<unsigned int*>(&h1);
    pack.z = *reinterpret_cast<unsigned int*>(&h2);
    pack.w = *reinterpret_cast<unsigned int*>(&h3);
    reinterpret_cast<uint4*>(g_comb)[i] = pack;
}

// ---------------------------------------------------------------------------
// Pass 2: one block per batch row, 128 threads.
//   warps 0-1 (t < 64):  stm half,  thread owns features [8*col, 8*col+8)
//   warps 2-3 (t >= 64): nstm half
// Inner loop per k: LDS.64 (packed {byte_off, half2 v}) + LDG.128 + 4 HFMA2.
// 2 half2-accumulator sets (16 terms each), merged in fp32.
// __launch_bounds__(128,14) caps regs at 36 -> ~87% occupancy.
// ---------------------------------------------------------------------------
__global__ __launch_bounds__(128, 14)
void nnue_kernel(const float*  __restrict__ values,
                 const int*    __restrict__ stm_idx,
                 const int*    __restrict__ nstm_idx,
                 const int*    __restrict__ buckets,
                 const float*  __restrict__ ft_b,
                 const float*  __restrict__ fft_b,
                 const float*  __restrict__ out_w,
                 const float*  __restrict__ out_b,
                 float*        __restrict__ out) {
    const int b = blockIdx.x;
    const int t = threadIdx.x;
    const int half_sel = t >> 6;       // 0 = stm, 1 = nstm
    const int col      = t & 63;       // feature group within the half

    __shared__ int2  pk[2][K_FEATS];   // {byte offset into g_comb, half2 value}
    __shared__ float red[4];

    {
        const int lane = t & 63;
        if (lane < K_FEATS) {
            const int side = t >> 6;
            const int* idx = side ? nstm_idx : stm_idx;
            int2 p;
            p.x = idx[b * K_FEATS + lane] * (FT_OUT * 2);   // byte offset
            __half2 v = __float2half2_rn(values[b * K_FEATS + lane]);
            p.y = *reinterpret_cast<int*>(&v);
            pk[side][lane] = p;
        }
    }
    __syncthreads();

    const char* base = reinterpret_cast<const char*>(g_comb) + col * 16;
    const int2* pp = pk[half_sel];

    __half2 acc[2][4];
    #pragma unroll
    for (int s = 0; s < 2; ++s)
        #pragma unroll
        for (int p = 0; p < 4; ++p)
            acc[s][p] = __float2half2_rn(0.f);

    #pragma unroll
    for (int k = 0; k < K_FEATS; ++k) {
        int2 p = pp[k];
        __half2 v2 = *reinterpret_cast<__half2*>(&p.y);
        uint4 w = *reinterpret_cast<const uint4*>(base + p.x);
        const __half2* wp = reinterpret_cast<const __half2*>(&w);
        const int s = k >> 4;          // compile-time under full unroll
        acc[s][0] = __hfma2(v2, wp[0], acc[s][0]);
        acc[s][1] = __hfma2(v2, wp[1], acc[s][1]);
        acc[s][2] = __hfma2(v2, wp[2], acc[s][2]);
        acc[s][3] = __hfma2(v2, wp[3], acc[s][3]);
    }

    // Merge accumulator sets in fp32
    float h[8];
    #pragma unroll
    for (int p = 0; p < 4; ++p) {
        float2 a0 = __half22float2(acc[0][p]);
        float2 a1 = __half22float2(acc[1][p]);
        h[2 * p]     = a0.x + a1.x;
        h[2 * p + 1] = a0.y + a1.y;
    }

    // bias (fp32) + clip to [0,1]
    const float4* bb = reinterpret_cast<const float4*>(ft_b)  + col * 2;
    const float4* fb = reinterpret_cast<const float4*>(fft_b) + col * 2;
    float4 b0 = bb[0], b1 = bb[1], f0 = fb[0], f1 = fb[1];
    h[0] += b0.x + f0.x;  h[1] += b0.y + f0.y;
    h[2] += b0.z + f0.z;  h[3] += b0.w + f0.w;
    h[4] += b1.x + f1.x;  h[5] += b1.y + f1.y;
    h[6] += b1.z + f1.z;  h[7] += b1.w + f1.w;
    #pragma unroll
    for (int i = 0; i < 8; ++i) h[i] = fminf(fmaxf(h[i], 0.f), 1.f);

    // dot with the selected bucket row of out_w [BUCKETS, 2*FT_OUT]
    const int bk = buckets[b];
    const float4* wrow = reinterpret_cast<const float4*>(
        out_w + bk * (2 * FT_OUT) + half_sel * FT_OUT) + col * 2;
    float4 w0 = wrow[0], w1 = wrow[1];

    float local = h[0] * w0.x + h[1] * w0.y + h[2] * w0.z + h[3] * w0.w
                + h[4] * w1.x + h[5] * w1.y + h[6] * w1.z + h[7] * w1.w;

    #pragma unroll
    for (int o = 16; o > 0; o >>= 1)
        local += __shfl_down_sync(0xffffffffu, local, o);
    if ((t & 31) == 0) red[t >> 5] = local;
    __syncthreads();
    if (t == 0) {
        float s = red[0] + red[1] + red[2] + red[3] + out_b[bk];
        out[b] = 1.0f / (1.0f + expf(-s));
    }
}

extern "C" void kernel_launch(void* const* d_in, const int* in_sizes, int n_in,
                              void* d_out, int out_size) {
    const float* values   = (const float*)d_in[0];
    const int*   stm_idx  = (const int*)  d_in[1];
    const int*   nstm_idx = (const int*)  d_in[2];
    const int*   buckets  = (const int*)  d_in[3];
    const float* ft_w     = (const float*)d_in[4];
    const float* ft_b     = (const float*)d_in[5];
    const float* fft_w    = (const float*)d_in[6];
    const float* fft_b    = (const float*)d_in[7];
    const float* out_w    = (const float*)d_in[8];
    const float* out_b    = (const float*)d_in[9];
    float* out = (float*)d_out;

    (void)in_sizes; (void)n_in; (void)out_size;

    const int ngroups = FT_VOCAB * (FT_OUT / 8);
    combine_kernel<<<(ngroups + 255) / 256, 256>>>(
        reinterpret_cast<const float4*>(ft_w),
        reinterpret_cast<const float4*>(fft_w));

    nnue_kernel<<<B_SIZE, 128>>>(values, stm_idx, nstm_idx, buckets,
                                 ft_b, fft_b, out_w, out_b, out);
}

// round 7
// speedup vs baseline: 1.0438x; 1.0438x over previous
#include <cuda_runtime.h>
#include <cuda_fp16.h>
#include <math.h>

#define B_SIZE    8192
#define K_FEATS   32
#define FT_OUT    512
#define BUCKETS   8
#define FT_VOCAB  40960
#define FFT_VOCAB 640

// Combined table quantized to int8 (biased-by-128 bytes) + per-row scale.
// comb[i][f] = ft_w[i][f] + fft_w[i%640][f]  ~=  (byte - 128) * g_scale[i]
// 40960 * 512 bytes = 21 MB (static __device__ scratch).
__device__ unsigned char g_comb8[FT_VOCAB * FT_OUT];
__device__ float         g_scale[FT_VOCAB];

// ---------------------------------------------------------------------------
// Pass 1: build quantized combined table. One block (128 thr) per vocab row.
// Thread t owns feats [4t, 4t+4). Block absmax reduction -> per-row scale.
// ---------------------------------------------------------------------------
__global__ __launch_bounds__(128)
void combine_q_kernel(const float4* __restrict__ ftw,
                      const float4* __restrict__ fftw) {
    const int row = blockIdx.x;
    const int t   = threadIdx.x;

    float4 a = __ldcs(ftw + (size_t)row * 128 + t);
    float4 bq = __ldg(fftw + (size_t)(row % FFT_VOCAB) * 128 + t);
    float c0 = a.x + bq.x, c1 = a.y + bq.y, c2 = a.z + bq.z, c3 = a.w + bq.w;

    float m = fmaxf(fmaxf(fabsf(c0), fabsf(c1)), fmaxf(fabsf(c2), fabsf(c3)));
    #pragma unroll
    for (int o = 16; o > 0; o >>= 1)
        m = fmaxf(m, __shfl_xor_sync(0xffffffffu, m, o));

    __shared__ float sm[4];
    if ((t & 31) == 0) sm[t >> 5] = m;
    __syncthreads();
    m = fmaxf(fmaxf(sm[0], sm[1]), fmaxf(sm[2], sm[3]));
    m = fmaxf(m, 1e-20f);

    const float inv = 127.0f / m;
    int q0 = __float2int_rn(c0 * inv) + 128;
    int q1 = __float2int_rn(c1 * inv) + 128;
    int q2 = __float2int_rn(c2 * inv) + 128;
    int q3 = __float2int_rn(c3 * inv) + 128;

    uchar4 pk = make_uchar4((unsigned char)q0, (unsigned char)q1,
                            (unsigned char)q2, (unsigned char)q3);
    reinterpret_cast<uchar4*>(g_comb8)[(size_t)row * 128 + t] = pk;
    if (t == 0) g_scale[row] = m * (1.0f / 127.0f);
}

// ---------------------------------------------------------------------------
// Pass 2: one block per batch row, 128 threads.
//   warps 0-1 (t < 64):  stm half,  thread owns feats [8*col, 8*col+8)
//   warps 2-3 (t >= 64): nstm half
// Hot loop per k: LDS.64 {byte_off, half2 vs} + LDG.64 (8 int8)
//               + 4 PRMT + 4 HSUB2 + 4 HFMA2.
// vs = value_k * row_scale_k premultiplied. Byte trick: half(0x6400|b) =
// 1024 + b exactly; subtract 1152 -> signed q in [-127,127].
// 2 half2-accumulator sets (16 terms each), merged in fp32.
// ---------------------------------------------------------------------------
__global__ __launch_bounds__(128, 12)
void nnue_kernel(const float*  __restrict__ values,
                 const int*    __restrict__ stm_idx,
                 const int*    __restrict__ nstm_idx,
                 const int*    __restrict__ buckets,
                 const float*  __restrict__ ft_b,
                 const float*  __restrict__ fft_b,
                 const float*  __restrict__ out_w,
                 const float*  __restrict__ out_b,
                 float*        __restrict__ out) {
    const int b = blockIdx.x;
    const int t = threadIdx.x;
    const int half_sel = t >> 6;
    const int col      = t & 63;

    __shared__ int2  pk[2][K_FEATS];   // {byte offset into g_comb8, half2 vs}
    __shared__ float red[4];

    {
        const int lane = t & 63;
        if (lane < K_FEATS) {
            const int side = t >> 6;
            const int* idxp = side ? nstm_idx : stm_idx;
            const int idx = idxp[b * K_FEATS + lane];
            int2 p;
            p.x = idx * FT_OUT;                          // byte offset (1B/elem)
            float vs = values[b * K_FEATS + lane] * g_scale[idx];
            __half2 v2 = __float2half2_rn(vs);
            p.y = *reinterpret_cast<int*>(&v2);
            pk[side][lane] = p;
        }
    }
    __syncthreads();

    const char* base = reinterpret_cast<const char*>(g_comb8) + col * 8;
    const int2* pp = pk[half_sel];

    const __half2 h1152 = __floats2half2_rn(1152.0f, 1152.0f);

    __half2 acc[2][4];
    #pragma unroll
    for (int s = 0; s < 2; ++s)
        #pragma unroll
        for (int p = 0; p < 4; ++p)
            acc[s][p] = __float2half2_rn(0.f);

    #pragma unroll
    for (int k = 0; k < K_FEATS; ++k) {
        int2 p = pp[k];
        __half2 vs2 = *reinterpret_cast<__half2*>(&p.y);
        uint2 u = *reinterpret_cast<const uint2*>(base + p.x);

        unsigned int ba = __byte_perm(u.x, 0x64646464u, 0x4140);
        unsigned int bb = __byte_perm(u.x, 0x64646464u, 0x4342);
        unsigned int bc = __byte_perm(u.y, 0x64646464u, 0x4140);
        unsigned int bd = __byte_perm(u.y, 0x64646464u, 0x4342);

        __half2 qa = __hsub2(*reinterpret_cast<__half2*>(&ba), h1152);
        __half2 qb = __hsub2(*reinterpret_cast<__half2*>(&bb), h1152);
        __half2 qc = __hsub2(*reinterpret_cast<__half2*>(&bc), h1152);
        __half2 qd = __hsub2(*reinterpret_cast<__half2*>(&bd), h1152);

        const int s = k >> 4;          // compile-time under full unroll
        acc[s][0] = __hfma2(vs2, qa, acc[s][0]);
        acc[s][1] = __hfma2(vs2, qb, acc[s][1]);
        acc[s][2] = __hfma2(vs2, qc, acc[s][2]);
        acc[s][3] = __hfma2(vs2, qd, acc[s][3]);
    }

    // Merge accumulator sets in fp32
    float h[8];
    #pragma unroll
    for (int p = 0; p < 4; ++p) {
        float2 a0 = __half22float2(acc[0][p]);
        float2 a1 = __half22float2(acc[1][p]);
        h[2 * p]     = a0.x + a1.x;
        h[2 * p + 1] = a0.y + a1.y;
    }

    // bias (fp32) + clip to [0,1]
    const float4* bb4 = reinterpret_cast<const float4*>(ft_b)  + col * 2;
    const float4* fb4 = reinterpret_cast<const float4*>(fft_b) + col * 2;
    float4 b0 = bb4[0], b1 = bb4[1], f0 = fb4[0], f1 = fb4[1];
    h[0] += b0.x + f0.x;  h[1] += b0.y + f0.y;
    h[2] += b0.z + f0.z;  h[3] += b0.w + f0.w;
    h[4] += b1.x + f1.x;  h[5] += b1.y + f1.y;
    h[6] += b1.z + f1.z;  h[7] += b1.w + f1.w;
    #pragma unroll
    for (int i = 0; i < 8; ++i) h[i] = fminf(fmaxf(h[i], 0.f), 1.f);

    // dot with the selected bucket row of out_w [BUCKETS, 2*FT_OUT]
    const int bk = buckets[b];
    const float4* wrow = reinterpret_cast<const float4*>(
        out_w + bk * (2 * FT_OUT) + half_sel * FT_OUT) + col * 2;
    float4 w0 = wrow[0], w1 = wrow[1];

    float local = h[0] * w0.x + h[1] * w0.y + h[2] * w0.z + h[3] * w0.w
                + h[4] * w1.x + h[5] * w1.y + h[6] * w1.z + h[7] * w1.w;

    #pragma unroll
    for (int o = 16; o > 0; o >>= 1)
        local += __shfl_down_sync(0xffffffffu, local, o);
    if ((t & 31) == 0) red[t >> 5] = local;
    __syncthreads();
    if (t == 0) {
        float s = red[0] + red[1] + red[2] + red[3] + out_b[bk];
        out[b] = 1.0f / (1.0f + expf(-s));
    }
}

extern "C" void kernel_launch(void* const* d_in, const int* in_sizes, int n_in,
                              void* d_out, int out_size) {
    const float* values   = (const float*)d_in[0];
    const int*   stm_idx  = (const int*)  d_in[1];
    const int*   nstm_idx = (const int*)  d_in[2];
    const int*   buckets  = (const int*)  d_in[3];
    const float* ft_w     = (const float*)d_in[4];
    const float* ft_b     = (const float*)d_in[5];
    const float* fft_w    = (const float*)d_in[6];
    const float* fft_b    = (const float*)d_in[7];
    const float* out_w    = (const float*)d_in[8];
    const float* out_b    = (const float*)d_in[9];
    float* out = (float*)d_out;

    (void)in_sizes; (void)n_in; (void)out_size;

    // Pass 1: quantized combined table, one block per vocab row
    combine_q_kernel<<<FT_VOCAB, 128>>>(
        reinterpret_cast<const float4*>(ft_w),
        reinterpret_cast<const float4*>(fft_w));

    // Pass 2: embedding-bag + bucketed head
    nnue_kernel<<<B_SIZE, 128>>>(values, stm_idx, nstm_idx, buckets,
                                 ft_b, fft_b, out_w, out_b, out);
}

// round 8
// speedup vs baseline: 1.1766x; 1.1272x over previous
#include <cuda_runtime.h>
#include <cuda_fp16.h>
#include <math.h>

#define B_SIZE    8192
#define K_FEATS   32
#define FT_OUT    512
#define BUCKETS   8
#define FT_VOCAB  40960
#define FFT_VOCAB 640

// Combined table quantized to int8 (biased-by-128 bytes) + per-row scale.
// comb[i][f] = ft_w[i][f] + fft_w[i%640][f]  ~=  (byte - 128) * g_scale[i]
__device__ unsigned char g_comb8[FT_VOCAB * FT_OUT];
__device__ float         g_scale[FT_VOCAB];

// ---------------------------------------------------------------------------
// Pass 1: quantize combined table. WARP-per-row: row (2 KB fp32) lives in
// registers (4 float4/lane), absmax via 5 shfls, no smem, no __syncthreads.
// 8 rows per 256-thread block. Loads & stores fully coalesced.
// ---------------------------------------------------------------------------
__global__ __launch_bounds__(256)
void combine_q_kernel(const float4* __restrict__ ftw,
                      const float4* __restrict__ fftw) {
    const int warp = threadIdx.x >> 5;
    const int lane = threadIdx.x & 31;
    const int row  = blockIdx.x * 8 + warp;

    const float4* fa = ftw  + (size_t)row * 128;
    const float4* fb = fftw + (size_t)(row % FFT_VOCAB) * 128;

    float4 c[4];
    #pragma unroll
    for (int i = 0; i < 4; ++i) {
        float4 a = __ldcs(fa + i * 32 + lane);      // streaming: don't pollute L2
        float4 b = __ldg(fb + i * 32 + lane);       // 1.3 MB: L2-resident
        c[i].x = a.x + b.x; c[i].y = a.y + b.y;
        c[i].z = a.z + b.z; c[i].w = a.w + b.w;
    }

    float m = 0.f;
    #pragma unroll
    for (int i = 0; i < 4; ++i)
        m = fmaxf(m, fmaxf(fmaxf(fabsf(c[i].x), fabsf(c[i].y)),
                           fmaxf(fabsf(c[i].z), fabsf(c[i].w))));
    #pragma unroll
    for (int o = 16; o > 0; o >>= 1)
        m = fmaxf(m, __shfl_xor_sync(0xffffffffu, m, o));
    m = fmaxf(m, 1e-20f);

    const float inv = 127.0f / m;
    uchar4* dst = reinterpret_cast<uchar4*>(g_comb8) + (size_t)row * 128;
    #pragma unroll
    for (int i = 0; i < 4; ++i) {
        uchar4 pk;
        pk.x = (unsigned char)(__float2int_rn(c[i].x * inv) + 128);
        pk.y = (unsigned char)(__float2int_rn(c[i].y * inv) + 128);
        pk.z = (unsigned char)(__float2int_rn(c[i].z * inv) + 128);
        pk.w = (unsigned char)(__float2int_rn(c[i].w * inv) + 128);
        dst[i * 32 + lane] = pk;
    }
    if (lane == 0) g_scale[row] = m * (1.0f / 127.0f);
}

// ---------------------------------------------------------------------------
// Pass 2: one block per batch row, 128 threads.
//   warps 0-1 (t < 64):  stm half,  thread owns feats [8*col, 8*col+8)
//   warps 2-3 (t >= 64): nstm half
// k-loop split into 4 chunks of 8: batch 8 LDG.64 gathers into registers
// (MLP=8 covers L2 hit latency), then decode (PRMT + HSUB2) + HFMA2.
// 2 half2-accumulator sets (16 terms each: chunks {0,1} / {2,3}), fp32 merge.
// No occupancy cap: let ptxas spend registers on the load batch.
// ---------------------------------------------------------------------------
__global__ __launch_bounds__(128)
void nnue_kernel(const float*  __restrict__ values,
                 const int*    __restrict__ stm_idx,
                 const int*    __restrict__ nstm_idx,
                 const int*    __restrict__ buckets,
                 const float*  __restrict__ ft_b,
                 const float*  __restrict__ fft_b,
                 const float*  __restrict__ out_w,
                 const float*  __restrict__ out_b,
                 float*        __restrict__ out) {
    const int b = blockIdx.x;
    const int t = threadIdx.x;
    const int half_sel = t >> 6;
    const int col      = t & 63;

    __shared__ int2  pk[2][K_FEATS];   // {byte offset into g_comb8, half2 vs}
    __shared__ float red[4];

    {
        const int lane = t & 63;
        if (lane < K_FEATS) {
            const int side = t >> 6;
            const int* idxp = side ? nstm_idx : stm_idx;
            const int idx = idxp[b * K_FEATS + lane];
            int2 p;
            p.x = idx * FT_OUT;                          // byte offset (1B/elem)
            float vs = values[b * K_FEATS + lane] * g_scale[idx];
            __half2 v2 = __float2half2_rn(vs);
            p.y = *reinterpret_cast<int*>(&v2);
            pk[side][lane] = p;
        }
    }
    __syncthreads();

    const char* base = reinterpret_cast<const char*>(g_comb8) + col * 8;
    const int2* pp = pk[half_sel];

    const __half2 h1152 = __floats2half2_rn(1152.0f, 1152.0f);

    __half2 acc[2][4];
    #pragma unroll
    for (int s = 0; s < 2; ++s)
        #pragma unroll
        for (int p = 0; p < 4; ++p)
            acc[s][p] = __float2half2_rn(0.f);

    #pragma unroll
    for (int c = 0; c < 4; ++c) {                // 4 chunks of 8 k-values
        uint2   u[8];
        __half2 vs[8];
        #pragma unroll
        for (int j = 0; j < 8; ++j) {            // batch 8 gathers (MLP=8)
            int2 p = pp[c * 8 + j];
            vs[j] = *reinterpret_cast<__half2*>(&p.y);
            u[j]  = *reinterpret_cast<const uint2*>(base + p.x);
        }
        const int s = c >> 1;                    // 16 terms per accumulator set
        #pragma unroll
        for (int j = 0; j < 8; ++j) {
            unsigned int ba = __byte_perm(u[j].x, 0x64646464u, 0x4140);
            unsigned int bb = __byte_perm(u[j].x, 0x64646464u, 0x4342);
            unsigned int bc = __byte_perm(u[j].y, 0x64646464u, 0x4140);
            unsigned int bd = __byte_perm(u[j].y, 0x64646464u, 0x4342);
            __half2 qa = __hsub2(*reinterpret_cast<__half2*>(&ba), h1152);
            __half2 qb = __hsub2(*reinterpret_cast<__half2*>(&bb), h1152);
            __half2 qc = __hsub2(*reinterpret_cast<__half2*>(&bc), h1152);
            __half2 qd = __hsub2(*reinterpret_cast<__half2*>(&bd), h1152);
            acc[s][0] = __hfma2(vs[j], qa, acc[s][0]);
            acc[s][1] = __hfma2(vs[j], qb, acc[s][1]);
            acc[s][2] = __hfma2(vs[j], qc, acc[s][2]);
            acc[s][3] = __hfma2(vs[j], qd, acc[s][3]);
        }
    }

    // Merge accumulator sets in fp32
    float h[8];
    #pragma unroll
    for (int p = 0; p < 4; ++p) {
        float2 a0 = __half22float2(acc[0][p]);
        float2 a1 = __half22float2(acc[1][p]);
        h[2 * p]     = a0.x + a1.x;
        h[2 * p + 1] = a0.y + a1.y;
    }

    // bias (fp32) + clip to [0,1]
    const float4* bb4 = reinterpret_cast<const float4*>(ft_b)  + col * 2;
    const float4* fb4 = reinterpret_cast<const float4*>(fft_b) + col * 2;
    float4 b0 = bb4[0], b1 = bb4[1], f0 = fb4[0], f1 = fb4[1];
    h[0] += b0.x + f0.x;  h[1] += b0.y + f0.y;
    h[2] += b0.z + f0.z;  h[3] += b0.w + f0.w;
    h[4] += b1.x + f1.x;  h[5] += b1.y + f1.y;
    h[6] += b1.z + f1.z;  h[7] += b1.w + f1.w;
    #pragma unroll
    for (int i = 0; i < 8; ++i) h[i] = fminf(fmaxf(h[i], 0.f), 1.f);

    // dot with the selected bucket row of out_w [BUCKETS, 2*FT_OUT]
    const int bk = buckets[b];
    const float4* wrow = reinterpret_cast<const float4*>(
        out_w + bk * (2 * FT_OUT) + half_sel * FT_OUT) + col * 2;
    float4 w0 = wrow[0], w1 = wrow[1];

    float local = h[0] * w0.x + h[1] * w0.y + h[2] * w0.z + h[3] * w0.w
                + h[4] * w1.x + h[5] * w1.y + h[6] * w1.z + h[7] * w1.w;

    #pragma unroll
    for (int o = 16; o > 0; o >>= 1)
        local += __shfl_down_sync(0xffffffffu, local, o);
    if ((t & 31) == 0) red[t >> 5] = local;
    __syncthreads();
    if (t == 0) {
        float s = red[0] + red[1] + red[2] + red[3] + out_b[bk];
        out[b] = 1.0f / (1.0f + expf(-s));
    }
}

extern "C" void kernel_launch(void* const* d_in, const int* in_sizes, int n_in,
                              void* d_out, int out_size) {
    const float* values   = (const float*)d_in[0];
    const int*   stm_idx  = (const int*)  d_in[1];
    const int*   nstm_idx = (const int*)  d_in[2];
    const int*   buckets  = (const int*)  d_in[3];
    const float* ft_w     = (const float*)d_in[4];
    const float* ft_b     = (const float*)d_in[5];
    const float* fft_w    = (const float*)d_in[6];
    const float* fft_b    = (const float*)d_in[7];
    const float* out_w    = (const float*)d_in[8];
    const float* out_b    = (const float*)d_in[9];
    float* out = (float*)d_out;

    (void)in_sizes; (void)n_in; (void)out_size;

    // Pass 1: quantized combined table, warp per vocab row
    combine_q_kernel<<<FT_VOCAB / 8, 256>>>(
        reinterpret_cast<const float4*>(ft_w),
        reinterpret_cast<const float4*>(fft_w));

    // Pass 2: embedding-bag + bucketed head
    nnue_kernel<<<B_SIZE, 128>>>(values, stm_idx, nstm_idx, buckets,
                                 ft_b, fft_b, out_w, out_b, out);
}

// round 9
// speedup vs baseline: 1.2351x; 1.0497x over previous
#include <cuda_runtime.h>
#include <cuda_fp16.h>
#include <math.h>

#define B_SIZE    8192
#define K_FEATS   32
#define FT_OUT    512
#define BUCKETS   8
#define FT_VOCAB  40960
#define FFT_VOCAB 640

// Combined table quantized to int8 (biased-by-128 bytes) + per-row scale.
// comb[i][f] = ft_w[i][f] + fft_w[i%640][f]  ~=  (byte - 128) * g_scale[i]
__device__ unsigned char g_comb8[FT_VOCAB * FT_OUT];
__device__ float         g_scale[FT_VOCAB];

__device__ __forceinline__ int dp4a_us(unsigned int a, int b, int c) {
    int d;
    asm("dp4a.u32.s32 %0, %1, %2, %3;" : "=r"(d) : "r"(a), "r"(b), "r"(c));
    return d;
}

// ---------------------------------------------------------------------------
// Pass 1: quantize combined table. Warp-per-row, register-resident, at the
// DRAM floor (~15 us). Unchanged from R7.
// ---------------------------------------------------------------------------
__global__ __launch_bounds__(256)
void combine_q_kernel(const float4* __restrict__ ftw,
                      const float4* __restrict__ fftw) {
    const int warp = threadIdx.x >> 5;
    const int lane = threadIdx.x & 31;
    const int row  = blockIdx.x * 8 + warp;

    const float4* fa = ftw  + (size_t)row * 128;
    const float4* fb = fftw + (size_t)(row % FFT_VOCAB) * 128;

    float4 c[4];
    #pragma unroll
    for (int i = 0; i < 4; ++i) {
        float4 a = __ldcs(fa + i * 32 + lane);
        float4 b = __ldg(fb + i * 32 + lane);
        c[i].x = a.x + b.x; c[i].y = a.y + b.y;
        c[i].z = a.z + b.z; c[i].w = a.w + b.w;
    }

    float m = 0.f;
    #pragma unroll
    for (int i = 0; i < 4; ++i)
        m = fmaxf(m, fmaxf(fmaxf(fabsf(c[i].x), fabsf(c[i].y)),
                           fmaxf(fabsf(c[i].z), fabsf(c[i].w))));
    #pragma unroll
    for (int o = 16; o > 0; o >>= 1)
        m = fmaxf(m, __shfl_xor_sync(0xffffffffu, m, o));
    m = fmaxf(m, 1e-20f);

    const float inv = 127.0f / m;
    uchar4* dst = reinterpret_cast<uchar4*>(g_comb8) + (size_t)row * 128;
    #pragma unroll
    for (int i = 0; i < 4; ++i) {
        uchar4 pk;
        pk.x = (unsigned char)(__float2int_rn(c[i].x * inv) + 128);
        pk.y = (unsigned char)(__float2int_rn(c[i].y * inv) + 128);
        pk.z = (unsigned char)(__float2int_rn(c[i].z * inv) + 128);
        pk.w = (unsigned char)(__float2int_rn(c[i].w * inv) + 128);
        dst[i * 32 + lane] = pk;
    }
    if (lane == 0) g_scale[row] = m * (1.0f / 127.0f);
}

// ---------------------------------------------------------------------------
// Pass 2: one block per batch row, 128 threads.
//   warps 0-1 (t < 64):  stm half,  thread owns feats [8*col, 8*col+8)
//   warps 2-3 (t >= 64): nstm half
// Per-k weights vs_k = value_k * row_scale_k quantized to int8 V_k with one
// per-(row,side) scale Sq (warp absmax). Hot loop per chunk of 4 k:
//   LDS.128 offsets + LDS.32 Vpack + 4x LDG.64 + 16 PRMT (byte transpose)
//   + 8 DP4A. Integer accumulation is exact; bias 128*sumV removed once.
// ---------------------------------------------------------------------------
__global__ __launch_bounds__(128)
void nnue_kernel(const float*  __restrict__ values,
                 const int*    __restrict__ stm_idx,
                 const int*    __restrict__ nstm_idx,
                 const int*    __restrict__ buckets,
                 const float*  __restrict__ ft_b,
                 const float*  __restrict__ fft_b,
                 const float*  __restrict__ out_w,
                 const float*  __restrict__ out_b,
                 float*        __restrict__ out) {
    const int b = blockIdx.x;
    const int t = threadIdx.x;
    const int half_sel = t >> 6;
    const int col      = t & 63;

    __shared__ int           offs[2][K_FEATS];
    __shared__ __align__(4) unsigned char sV[2][K_FEATS];
    __shared__ float sSq[2];
    __shared__ int   sSumV[2];
    __shared__ float red[4];

    {
        const int wid  = t >> 5;           // warp 0 -> stm, warp 2 -> nstm
        const int lane = t & 31;
        if ((wid & 1) == 0) {
            const int side = wid >> 1;
            const int* idxp = side ? nstm_idx : stm_idx;
            const int idx = idxp[b * K_FEATS + lane];
            offs[side][lane] = idx * FT_OUT;
            float vs = values[b * K_FEATS + lane] * g_scale[idx];

            // warp absmax -> per-side scale
            float m = fabsf(vs);
            #pragma unroll
            for (int o = 16; o > 0; o >>= 1)
                m = fmaxf(m, __shfl_xor_sync(0xffffffffu, m, o));
            float Sq = fmaxf(m, 1e-30f) * (1.0f / 127.0f);

            int V = __float2int_rn(vs / Sq);          // in [-127,127]
            sV[side][lane] = (unsigned char)(V & 0xff);

            int sv = V;
            #pragma unroll
            for (int o = 16; o > 0; o >>= 1)
                sv += __shfl_xor_sync(0xffffffffu, sv, o);
            if (lane == 0) { sSq[side] = Sq; sSumV[side] = sv; }
        }
    }
    __syncthreads();

    const char* base = reinterpret_cast<const char*>(g_comb8) + col * 8;
    const int*  offp = offs[half_sel];
    const int*  vpk  = reinterpret_cast<const int*>(sV[half_sel]);

    int acc[8];
    #pragma unroll
    for (int f = 0; f < 8; ++f) acc[f] = 0;

    #pragma unroll
    for (int c = 0; c < 8; ++c) {                    // 8 chunks of 4 k-values
        int4 o4 = *reinterpret_cast<const int4*>(offp + c * 4);
        int  Vp = vpk[c];                            // {V(k0..k3)} packed s8
        uint2 u0 = *reinterpret_cast<const uint2*>(base + o4.x);
        uint2 u1 = *reinterpret_cast<const uint2*>(base + o4.y);
        uint2 u2 = *reinterpret_cast<const uint2*>(base + o4.z);
        uint2 u3 = *reinterpret_cast<const uint2*>(base + o4.w);

        // byte-transpose: r_f = {b_f(k0), b_f(k1), b_f(k2), b_f(k3)}
        unsigned ta = __byte_perm(u0.x, u1.x, 0x5140);
        unsigned tb = __byte_perm(u2.x, u3.x, 0x5140);
        unsigned tc = __byte_perm(u0.x, u1.x, 0x7362);
        unsigned td = __byte_perm(u2.x, u3.x, 0x7362);
        acc[0] = dp4a_us(__byte_perm(ta, tb, 0x5410), Vp, acc[0]);
        acc[1] = dp4a_us(__byte_perm(ta, tb, 0x7632), Vp, acc[1]);
        acc[2] = dp4a_us(__byte_perm(tc, td, 0x5410), Vp, acc[2]);
        acc[3] = dp4a_us(__byte_perm(tc, td, 0x7632), Vp, acc[3]);

        ta = __byte_perm(u0.y, u1.y, 0x5140);
        tb = __byte_perm(u2.y, u3.y, 0x5140);
        tc = __byte_perm(u0.y, u1.y, 0x7362);
        td = __byte_perm(u2.y, u3.y, 0x7362);
        acc[4] = dp4a_us(__byte_perm(ta, tb, 0x5410), Vp, acc[4]);
        acc[5] = dp4a_us(__byte_perm(ta, tb, 0x7632), Vp, acc[5]);
        acc[6] = dp4a_us(__byte_perm(tc, td, 0x5410), Vp, acc[6]);
        acc[7] = dp4a_us(__byte_perm(tc, td, 0x7632), Vp, acc[7]);
    }

    // Undo +128 byte bias exactly, scale, add biases, clip.
    const float Sq   = sSq[half_sel];
    const int   corr = 128 * sSumV[half_sel];

    const float4* bb4 = reinterpret_cast<const float4*>(ft_b)  + col * 2;
    const float4* fb4 = reinterpret_cast<const float4*>(fft_b) + col * 2;
    float4 b0 = bb4[0], b1 = bb4[1], f0 = fb4[0], f1 = fb4[1];
    float bias[8] = { b0.x + f0.x, b0.y + f0.y, b0.z + f0.z, b0.w + f0.w,
                      b1.x + f1.x, b1.y + f1.y, b1.z + f1.z, b1.w + f1.w };

    float h[8];
    #pragma unroll
    for (int f = 0; f < 8; ++f) {
        h[f] = (float)(acc[f] - corr) * Sq + bias[f];
        h[f] = fminf(fmaxf(h[f], 0.f), 1.f);
    }

    // dot with the selected bucket row of out_w [BUCKETS, 2*FT_OUT]
    const int bk = buckets[b];
    const float4* wrow = reinterpret_cast<const float4*>(
        out_w + bk * (2 * FT_OUT) + half_sel * FT_OUT) + col * 2;
    float4 w0 = wrow[0], w1 = wrow[1];

    float local = h[0] * w0.x + h[1] * w0.y + h[2] * w0.z + h[3] * w0.w
                + h[4] * w1.x + h[5] * w1.y + h[6] * w1.z + h[7] * w1.w;

    #pragma unroll
    for (int o = 16; o > 0; o >>= 1)
        local += __shfl_down_sync(0xffffffffu, local, o);
    if ((t & 31) == 0) red[t >> 5] = local;
    __syncthreads();
    if (t == 0) {
        float s = red[0] + red[1] + red[2] + red[3] + out_b[bk];
        out[b] = 1.0f / (1.0f + expf(-s));
    }
}

extern "C" void kernel_launch(void* const* d_in, const int* in_sizes, int n_in,
                              void* d_out, int out_size) {
    const float* values   = (const float*)d_in[0];
    const int*   stm_idx  = (const int*)  d_in[1];
    const int*   nstm_idx = (const int*)  d_in[2];
    const int*   buckets  = (const int*)  d_in[3];
    const float* ft_w     = (const float*)d_in[4];
    const float* ft_b     = (const float*)d_in[5];
    const float* fft_w    = (const float*)d_in[6];
    const float* fft_b    = (const float*)d_in[7];
    const float* out_w    = (const float*)d_in[8];
    const float* out_b    = (const float*)d_in[9];
    float* out = (float*)d_out;

    (void)in_sizes; (void)n_in; (void)out_size;

    combine_q_kernel<<<FT_VOCAB / 8, 256>>>(
        reinterpret_cast<const float4*>(ft_w),
        reinterpret_cast<const float4*>(fft_w));

    nnue_kernel<<<B_SIZE, 128>>>(values, stm_idx, nstm_idx, buckets,
                                 ft_b, fft_b, out_w, out_b, out);
}